// round 11
// baseline (speedup 1.0000x reference)
#include <cuda_runtime.h>
#include <cuda_bf16.h>
#include <mma.h>
#include <cstdint>

using namespace nvcuda;

#define NN 50000
#define NE 800000
#define L 128
#define KEFF 24   // 16 node feats + 3 agg_s + 1 cnt_s + 3 agg_r + 1 cnt_r
#define NB 782    // node CTAs: 782*64 = 50048

// Scratch (__device__ globals; no allocation allowed)
__device__ float g_agg[NN * 8];    // per node: {s0,s1,s2,cnt_s, r0,r1,r2,cnt_r}
__device__ float g_b1eff[L];       // folded layer-1 bias
__device__ float g_w2d[L];         // W2 @ W_dn
__device__ float g_cd[1];          // b2.W_dn + b_dn
// bf16 hi/lo folded layer-1 weights: row j (128), cols [whi(24)+pad8 | wlo(24)+pad8]
__device__ __align__(16) __nv_bfloat16 g_W1b[L * 64];   // 16 KB

__device__ __forceinline__ float warp_sum(float v) {
#pragma unroll
    for (int o = 16; o; o >>= 1) v += __shfl_xor_sync(0xffffffffu, v, o);
    return v;
}

// ---------------------------------------------------------------------------
// Edge pass + embedded prep folds. Fold warps emit bf16 hi/lo weight rows.
__global__ __launch_bounds__(256) void edge_kernel(
    const float* __restrict__ edges, const int* __restrict__ senders,
    const int* __restrict__ receivers, float* __restrict__ edges_out,
    const float* __restrict__ g, const float* __restrict__ W_en,
    const float* __restrict__ b_en, const float* __restrict__ W_ee,
    const float* __restrict__ b_ee, const float* __restrict__ W1,
    const float* __restrict__ b1, const float* __restrict__ W2,
    const float* __restrict__ b2, const float* __restrict__ W_dn,
    const float* __restrict__ b_dn, const float* __restrict__ W_de,
    const float* __restrict__ b_de) {
    __shared__ float s_edec[4];
    int tid = threadIdx.x;
    int lane = tid & 31;
    int warp = tid >> 5;

    if (warp < 4) {
        float acc = 0.f;
        const float* A = (warp < 3) ? (W_ee + warp * L) : b_ee;
#pragma unroll
        for (int q = 0; q < 4; q++) {
            int m = lane + 32 * q;
            acc += A[m] * W_de[m];
        }
        acc = warp_sum(acc);
        if (lane == 0) s_edec[warp] = (warp == 3) ? acc + b_de[0] : acc;
    }

    int gw = blockIdx.x * 8 + warp;
    if (gw < L * KEFF) {  // W1eff[j][k] -> bf16 hi/lo
        int k = gw >> 7;
        int j = gw & (L - 1);
        const float* A;
        int base;
        if (k < 16)      { A = W_en + k * L;        base = 0; }
        else if (k < 19) { A = W_ee + (k - 16) * L; base = L; }
        else if (k == 19){ A = b_ee;                base = L; }
        else if (k < 23) { A = W_ee + (k - 20) * L; base = 2 * L; }
        else             { A = b_ee;                base = 2 * L; }
        float acc = 0.f;
#pragma unroll
        for (int q = 0; q < 4; q++) {
            int m = lane + 32 * q;
            acc += A[m] * W1[(size_t)(base + m) * L + j];
        }
        acc = warp_sum(acc);
        if (lane == 0) {
            __nv_bfloat16 whi = __float2bfloat16(acc);
            __nv_bfloat16 wlo = __float2bfloat16(acc - __bfloat162float(whi));
            g_W1b[j * 64 + k] = whi;
            g_W1b[j * 64 + 32 + k] = wlo;
        }
    } else if (gw < L * KEFF + L) {
        int j = gw - L * KEFF;
        float acc = 0.f;
#pragma unroll
        for (int q = 0; q < 4; q++) {
            int m = lane + 32 * q;
            acc += b_en[m] * W1[(size_t)m * L + j];
        }
        if (lane < 8) acc += g[lane] * W1[(size_t)(3 * L + lane) * L + j];
        acc = warp_sum(acc);
        if (lane == 0) g_b1eff[j] = acc + b1[j];
    } else if (gw < L * KEFF + 2 * L) {
        int k = gw - L * KEFF - L;
        float acc = 0.f;
#pragma unroll
        for (int q = 0; q < 4; q++) {
            int j = lane + 32 * q;
            acc += W2[(size_t)k * L + j] * W_dn[j];
        }
        acc = warp_sum(acc);
        if (lane == 0) g_w2d[k] = acc;
    } else if (gw == L * KEFF + 2 * L) {
        float acc = 0.f;
#pragma unroll
        for (int q = 0; q < 4; q++) {
            int j = lane + 32 * q;
            acc += b2[j] * W_dn[j];
        }
        acc = warp_sum(acc);
        if (lane == 0) g_cd[0] = acc + b_dn[0];
    }
    __syncthreads();

    int e = blockIdx.x * blockDim.x + tid;
    if (e >= NE) return;

    float w0 = s_edec[0], w1 = s_edec[1], w2 = s_edec[2], c = s_edec[3];

    float x0 = __ldg(edges + 3 * e + 0);
    float x1 = __ldg(edges + 3 * e + 1);
    float x2 = __ldg(edges + 3 * e + 2);
    int s = senders[e];
    int r = receivers[e];

    float* ps = g_agg + (size_t)8 * s;
    float* pr = g_agg + (size_t)8 * r + 4;
    asm volatile("red.global.add.v4.f32 [%0], {%1, %2, %3, %4};" ::"l"(ps),
                 "f"(x0), "f"(x1), "f"(x2), "f"(1.0f)
                 : "memory");
    asm volatile("red.global.add.v4.f32 [%0], {%1, %2, %3, %4};" ::"l"(pr),
                 "f"(x0), "f"(x1), "f"(x2), "f"(1.0f)
                 : "memory");

    edges_out[e] = fmaf(x0, w0, fmaf(x1, w1, fmaf(x2, w2, c)));
}

// ---------------------------------------------------------------------------
// Node pass via wmma (HMMA, baseline sm_80+ path):
// CTA = 64 nodes, 4 warps; warp w owns nodes [w*16, w*16+16), all 128 j.
// A smem [64][64] bf16 = [xhi(32pad) | xlo(32)],  B smem [128][64] = [whi|wlo].
// D = xhi.whi + xlo.whi + xhi.wlo  (6 wmma per 16x16 n-tile, fp32 accum).
// Epilogue: +b1eff, relu, dot w2d, +cd.
#define DS_LD 132  // f32 row stride for D scratch (132%32=4 words -> conflict-light)

__global__ __launch_bounds__(128) void node_tc_kernel(
    const float* __restrict__ nodes, float* __restrict__ nodes_out) {
    __shared__ __align__(16) __nv_bfloat16 As[64 * 64];   // 8 KB
    __shared__ __align__(16) __nv_bfloat16 Bs[L * 64];    // 16 KB
    __shared__ float Ds[64 * DS_LD];                      // 33 KB
    __shared__ float sB1e[L];
    __shared__ float sDv[L];

    int tid = threadIdx.x;
    int wid = tid >> 5;

    // copy weights (byte-identical) + bias/decoder vectors
    {
        const uint4* s = reinterpret_cast<const uint4*>(g_W1b);
        uint4* d = reinterpret_cast<uint4*>(Bs);
        for (int i = tid; i < L * 64 * 2 / 16; i += 128) d[i] = s[i];
        sB1e[tid] = g_b1eff[tid];
        sDv[tid] = g_w2d[tid];
    }

    // stage A: threads 0..63, one node row each
    if (tid < 64) {
        int node = blockIdx.x * 64 + tid;
        float x[32];
#pragma unroll
        for (int k = 0; k < 32; k++) x[k] = 0.f;
        if (node < NN) {
            const float4* np =
                reinterpret_cast<const float4*>(nodes + (size_t)node * 16);
#pragma unroll
            for (int q = 0; q < 4; q++) {
                float4 v = __ldg(np + q);
                x[4 * q + 0] = v.x; x[4 * q + 1] = v.y;
                x[4 * q + 2] = v.z; x[4 * q + 3] = v.w;
            }
            const float4* pa =
                reinterpret_cast<const float4*>(g_agg + (size_t)8 * node);
            float4 a0 = pa[0], a1 = pa[1];
            x[16] = a0.x; x[17] = a0.y; x[18] = a0.z; x[19] = a0.w;
            x[20] = a1.x; x[21] = a1.y; x[22] = a1.z; x[23] = a1.w;
        }
        __nv_bfloat16* arow = As + tid * 64;
#pragma unroll
        for (int k = 0; k < 32; k++) {
            __nv_bfloat16 h = __float2bfloat16(x[k]);
            arow[k] = h;
            arow[32 + k] = __float2bfloat16(x[k] - __bfloat162float(h));
        }
    }
    __syncthreads();

    // per-warp wmma: A row-major, B col-major (Bs[j][k] => B(k,j) with ld 64)
    wmma::fragment<wmma::matrix_a, 16, 16, 16, __nv_bfloat16, wmma::row_major>
        a0, a1, a2, a3;
    const __nv_bfloat16* abase = As + wid * 16 * 64;
    wmma::load_matrix_sync(a0, abase + 0, 64);   // xhi k 0..15
    wmma::load_matrix_sync(a1, abase + 16, 64);  // xhi k 16..31
    wmma::load_matrix_sync(a2, abase + 32, 64);  // xlo k 0..15
    wmma::load_matrix_sync(a3, abase + 48, 64);  // xlo k 16..31

#pragma unroll
    for (int nt = 0; nt < 8; nt++) {
        wmma::fragment<wmma::accumulator, 16, 16, 16, float> acc;
        wmma::fill_fragment(acc, 0.f);
        wmma::fragment<wmma::matrix_b, 16, 16, 16, __nv_bfloat16,
                       wmma::col_major> bh0, bh1, bl0, bl1;
        const __nv_bfloat16* bbase = Bs + nt * 16 * 64;
        wmma::load_matrix_sync(bh0, bbase + 0, 64);   // whi k 0..15
        wmma::load_matrix_sync(bh1, bbase + 16, 64);  // whi k 16..31
        wmma::load_matrix_sync(bl0, bbase + 32, 64);  // wlo k 0..15
        wmma::load_matrix_sync(bl1, bbase + 48, 64);  // wlo k 16..31
        wmma::mma_sync(acc, a0, bh0, acc);  // xhi.whi
        wmma::mma_sync(acc, a1, bh1, acc);
        wmma::mma_sync(acc, a2, bh0, acc);  // xlo.whi
        wmma::mma_sync(acc, a3, bh1, acc);
        wmma::mma_sync(acc, a0, bl0, acc);  // xhi.wlo
        wmma::mma_sync(acc, a1, bl1, acc);
        wmma::store_matrix_sync(Ds + wid * 16 * DS_LD + nt * 16, acc, DS_LD,
                                wmma::mem_row_major);
    }
    __syncthreads();

    // epilogue: 2 threads per node row
    int row = tid >> 1;
    int half = tid & 1;
    const float* drow = Ds + row * DS_LD + half * 64;
    const float* bvec = sB1e + half * 64;
    const float* dvec = sDv + half * 64;
    float s = 0.f;
#pragma unroll 8
    for (int jj = 0; jj < 64; jj++) {
        float h = drow[jj] + bvec[jj];
        s = fmaf(fmaxf(h, 0.f), dvec[jj], s);
    }
    s += __shfl_xor_sync(0xffffffffu, s, 1);
    if (half == 0) {
        int node = blockIdx.x * 64 + row;
        if (node < NN) nodes_out[node] = s + g_cd[0];
    }
}

// ---------------------------------------------------------------------------
extern "C" void kernel_launch(void* const* d_in, const int* in_sizes, int n_in,
                              void* d_out, int out_size) {
    const float* nodes     = (const float*)d_in[0];
    const float* edges     = (const float*)d_in[1];
    const float* globals_  = (const float*)d_in[2];
    const int*   senders   = (const int*)d_in[3];
    const int*   receivers = (const int*)d_in[4];
    const float* W_en = (const float*)d_in[5];
    const float* b_en = (const float*)d_in[6];
    const float* W_ee = (const float*)d_in[7];
    const float* b_ee = (const float*)d_in[8];
    const float* W1   = (const float*)d_in[9];
    const float* b1   = (const float*)d_in[10];
    const float* W2   = (const float*)d_in[11];
    const float* b2   = (const float*)d_in[12];
    const float* W_dn = (const float*)d_in[13];
    const float* b_dn = (const float*)d_in[14];
    const float* W_de = (const float*)d_in[15];
    const float* b_de = (const float*)d_in[16];

    float* out = (float*)d_out;
    float* nodes_out = out;          // [50000]
    float* edges_out = out + NN;     // [800000]

    void* p = nullptr;
    cudaGetSymbolAddress(&p, g_agg);
    cudaMemsetAsync(p, 0, (size_t)NN * 8 * sizeof(float), 0);
    cudaGetSymbolAddress(&p, g_W1b);
    cudaMemsetAsync(p, 0, L * 64 * sizeof(__nv_bfloat16), 0);

    edge_kernel<<<(NE + 255) / 256, 256>>>(
        edges, senders, receivers, edges_out, globals_, W_en, b_en, W_ee, b_ee,
        W1, b1, W2, b2, W_dn, b_dn, W_de, b_de);
    node_tc_kernel<<<NB, 128>>>(nodes, nodes_out);
}

// round 13
// speedup vs baseline: 1.0306x; 1.0306x over previous
#include <cuda_runtime.h>
#include <cuda_bf16.h>
#include <mma.h>
#include <cstdint>

using namespace nvcuda;

#define NN 50000
#define NE 800000
#define L 128
#define KEFF 24   // 16 node feats + 3 agg_s + 1 cnt_s + 3 agg_r + 1 cnt_r
#define NB 782    // node CTAs: 782*64 = 50048
#define TLD 20    // per-warp epilogue tile leading dim (fp32; MUST be mult of 4)

// Scratch (__device__ globals; no allocation allowed)
__device__ float g_agg[NN * 8];    // per node: {s0,s1,s2,cnt_s, r0,r1,r2,cnt_r}
__device__ float g_b1eff[L];       // folded layer-1 bias
__device__ float g_w2d[L];         // W2 @ W_dn
__device__ float g_cd[1];          // b2.W_dn + b_dn
// bf16 hi/lo folded layer-1 weights: row j (128), cols [whi(24)+pad8 | wlo(24)+pad8]
__device__ __align__(16) __nv_bfloat16 g_W1b[L * 64];   // 16 KB

__device__ __forceinline__ float warp_sum(float v) {
#pragma unroll
    for (int o = 16; o; o >>= 1) v += __shfl_xor_sync(0xffffffffu, v, o);
    return v;
}

// ---------------------------------------------------------------------------
// Edge pass + embedded prep folds. Fold warps emit bf16 hi/lo weight rows.
__global__ __launch_bounds__(256) void edge_kernel(
    const float* __restrict__ edges, const int* __restrict__ senders,
    const int* __restrict__ receivers, float* __restrict__ edges_out,
    const float* __restrict__ g, const float* __restrict__ W_en,
    const float* __restrict__ b_en, const float* __restrict__ W_ee,
    const float* __restrict__ b_ee, const float* __restrict__ W1,
    const float* __restrict__ b1, const float* __restrict__ W2,
    const float* __restrict__ b2, const float* __restrict__ W_dn,
    const float* __restrict__ b_dn, const float* __restrict__ W_de,
    const float* __restrict__ b_de) {
    __shared__ float s_edec[4];
    int tid = threadIdx.x;
    int lane = tid & 31;
    int warp = tid >> 5;

    if (warp < 4) {
        float acc = 0.f;
        const float* A = (warp < 3) ? (W_ee + warp * L) : b_ee;
#pragma unroll
        for (int q = 0; q < 4; q++) {
            int m = lane + 32 * q;
            acc += A[m] * W_de[m];
        }
        acc = warp_sum(acc);
        if (lane == 0) s_edec[warp] = (warp == 3) ? acc + b_de[0] : acc;
    }

    int gw = blockIdx.x * 8 + warp;
    if (gw < L * KEFF) {  // W1eff[j][k] -> bf16 hi/lo
        int k = gw >> 7;
        int j = gw & (L - 1);
        const float* A;
        int base;
        if (k < 16)      { A = W_en + k * L;        base = 0; }
        else if (k < 19) { A = W_ee + (k - 16) * L; base = L; }
        else if (k == 19){ A = b_ee;                base = L; }
        else if (k < 23) { A = W_ee + (k - 20) * L; base = 2 * L; }
        else             { A = b_ee;                base = 2 * L; }
        float acc = 0.f;
#pragma unroll
        for (int q = 0; q < 4; q++) {
            int m = lane + 32 * q;
            acc += A[m] * W1[(size_t)(base + m) * L + j];
        }
        acc = warp_sum(acc);
        if (lane == 0) {
            __nv_bfloat16 whi = __float2bfloat16(acc);
            __nv_bfloat16 wlo = __float2bfloat16(acc - __bfloat162float(whi));
            g_W1b[j * 64 + k] = whi;
            g_W1b[j * 64 + 32 + k] = wlo;
        }
    } else if (gw < L * KEFF + L) {
        int j = gw - L * KEFF;
        float acc = 0.f;
#pragma unroll
        for (int q = 0; q < 4; q++) {
            int m = lane + 32 * q;
            acc += b_en[m] * W1[(size_t)m * L + j];
        }
        if (lane < 8) acc += g[lane] * W1[(size_t)(3 * L + lane) * L + j];
        acc = warp_sum(acc);
        if (lane == 0) g_b1eff[j] = acc + b1[j];
    } else if (gw < L * KEFF + 2 * L) {
        int k = gw - L * KEFF - L;
        float acc = 0.f;
#pragma unroll
        for (int q = 0; q < 4; q++) {
            int j = lane + 32 * q;
            acc += W2[(size_t)k * L + j] * W_dn[j];
        }
        acc = warp_sum(acc);
        if (lane == 0) g_w2d[k] = acc;
    } else if (gw == L * KEFF + 2 * L) {
        float acc = 0.f;
#pragma unroll
        for (int q = 0; q < 4; q++) {
            int j = lane + 32 * q;
            acc += b2[j] * W_dn[j];
        }
        acc = warp_sum(acc);
        if (lane == 0) g_cd[0] = acc + b_dn[0];
    }
    __syncthreads();

    int e = blockIdx.x * blockDim.x + tid;
    if (e >= NE) return;

    float w0 = s_edec[0], w1 = s_edec[1], w2 = s_edec[2], c = s_edec[3];

    float x0 = __ldg(edges + 3 * e + 0);
    float x1 = __ldg(edges + 3 * e + 1);
    float x2 = __ldg(edges + 3 * e + 2);
    int s = senders[e];
    int r = receivers[e];

    float* ps = g_agg + (size_t)8 * s;
    float* pr = g_agg + (size_t)8 * r + 4;
    asm volatile("red.global.add.v4.f32 [%0], {%1, %2, %3, %4};" ::"l"(ps),
                 "f"(x0), "f"(x1), "f"(x2), "f"(1.0f)
                 : "memory");
    asm volatile("red.global.add.v4.f32 [%0], {%1, %2, %3, %4};" ::"l"(pr),
                 "f"(x0), "f"(x1), "f"(x2), "f"(1.0f)
                 : "memory");

    edges_out[e] = fmaf(x0, w0, fmaf(x1, w1, fmaf(x2, w2, c)));
}

// ---------------------------------------------------------------------------
// Node pass via wmma: CTA = 64 nodes, 4 warps; warp w owns nodes
// [w*16, w*16+16) x all 128 j. Per j-tile: 4 B frag loads, two independent
// 3-deep HMMA chains (accE/accO), fragment add, store 16x16 into a per-warp
// smem tile (TLD=20, legal mult-of-4 stride), immediate in-warp epilogue.
// No block-wide D buffer, no block syncs after staging.
__global__ __launch_bounds__(128) void node_tc_kernel(
    const float* __restrict__ nodes, float* __restrict__ nodes_out) {
    __shared__ __align__(16) __nv_bfloat16 As[64 * 64];   // 8 KB
    __shared__ __align__(16) __nv_bfloat16 Bs[L * 64];    // 16 KB
    __shared__ __align__(16) float Ts[4][16 * TLD];       // 4 x 1.25 KB
    __shared__ float sB1e[L];
    __shared__ float sDv[L];

    int tid = threadIdx.x;
    int wid = tid >> 5;
    int lane = tid & 31;

    // copy weights (byte-identical) + bias/decoder vectors
    {
        const uint4* s = reinterpret_cast<const uint4*>(g_W1b);
        uint4* d = reinterpret_cast<uint4*>(Bs);
        for (int i = tid; i < L * 64 * 2 / 16; i += 128) d[i] = s[i];
        sB1e[tid] = g_b1eff[tid];
        sDv[tid] = g_w2d[tid];
    }

    // stage A: threads 0..63, one node row each
    if (tid < 64) {
        int node = blockIdx.x * 64 + tid;
        float x[32];
#pragma unroll
        for (int k = 0; k < 32; k++) x[k] = 0.f;
        if (node < NN) {
            const float4* np =
                reinterpret_cast<const float4*>(nodes + (size_t)node * 16);
#pragma unroll
            for (int q = 0; q < 4; q++) {
                float4 v = __ldg(np + q);
                x[4 * q + 0] = v.x; x[4 * q + 1] = v.y;
                x[4 * q + 2] = v.z; x[4 * q + 3] = v.w;
            }
            const float4* pa =
                reinterpret_cast<const float4*>(g_agg + (size_t)8 * node);
            float4 a0 = pa[0], a1 = pa[1];
            x[16] = a0.x; x[17] = a0.y; x[18] = a0.z; x[19] = a0.w;
            x[20] = a1.x; x[21] = a1.y; x[22] = a1.z; x[23] = a1.w;
        }
        __nv_bfloat16* arow = As + tid * 64;
#pragma unroll
        for (int k = 0; k < 32; k++) {
            __nv_bfloat16 h = __float2bfloat16(x[k]);
            arow[k] = h;
            arow[32 + k] = __float2bfloat16(x[k] - __bfloat162float(h));
        }
    }
    __syncthreads();

    // A fragments (row-major), loaded once per warp
    wmma::fragment<wmma::matrix_a, 16, 16, 16, __nv_bfloat16, wmma::row_major>
        a0, a1, a2, a3;
    const __nv_bfloat16* abase = As + wid * 16 * 64;
    wmma::load_matrix_sync(a0, abase + 0, 64);   // xhi k 0..15
    wmma::load_matrix_sync(a1, abase + 16, 64);  // xhi k 16..31
    wmma::load_matrix_sync(a2, abase + 32, 64);  // xlo k 0..15
    wmma::load_matrix_sync(a3, abase + 48, 64);  // xlo k 16..31

    // epilogue lane mapping: row = lane>>1, j-half-of-8 = lane&1
    int erow = lane >> 1;
    int ejh = (lane & 1) * 8;
    float* tbuf = Ts[wid];
    float spart = 0.f;

#pragma unroll
    for (int nt = 0; nt < 8; nt++) {
        wmma::fragment<wmma::matrix_b, 16, 16, 16, __nv_bfloat16,
                       wmma::col_major> bh0, bh1, bl0, bl1;
        const __nv_bfloat16* bbase = Bs + nt * 16 * 64;
        wmma::load_matrix_sync(bh0, bbase + 0, 64);   // whi k 0..15
        wmma::load_matrix_sync(bh1, bbase + 16, 64);  // whi k 16..31
        wmma::load_matrix_sync(bl0, bbase + 32, 64);  // wlo k 0..15
        wmma::load_matrix_sync(bl1, bbase + 48, 64);  // wlo k 16..31

        wmma::fragment<wmma::accumulator, 16, 16, 16, float> accE, accO;
        wmma::fill_fragment(accE, 0.f);
        wmma::fill_fragment(accO, 0.f);
        // two independent 3-deep chains
        wmma::mma_sync(accE, a0, bh0, accE);  // xhi.whi (k lo)
        wmma::mma_sync(accO, a1, bh1, accO);  // xhi.whi (k hi)
        wmma::mma_sync(accE, a2, bh0, accE);  // xlo.whi
        wmma::mma_sync(accO, a3, bh1, accO);
        wmma::mma_sync(accE, a0, bl0, accE);  // xhi.wlo
        wmma::mma_sync(accO, a1, bl1, accO);
#pragma unroll
        for (int i = 0; i < accE.num_elements; i++) accE.x[i] += accO.x[i];

        wmma::store_matrix_sync(tbuf, accE, TLD, wmma::mem_row_major);
        __syncwarp();

        // in-warp epilogue for this 16-j tile
        const float* dr = tbuf + erow * TLD + ejh;
        const float* bv = sB1e + nt * 16 + ejh;
        const float* dv = sDv + nt * 16 + ejh;
#pragma unroll
        for (int i = 0; i < 8; i++) {
            float h = dr[i] + bv[i];
            spart = fmaf(fmaxf(h, 0.f), dv[i], spart);
        }
        __syncwarp();  // protect tbuf before next tile's store
    }

    // combine the two j-halves (lanes 2r, 2r+1) and write
    spart += __shfl_xor_sync(0xffffffffu, spart, 1);
    if ((lane & 1) == 0) {
        int node = blockIdx.x * 64 + wid * 16 + erow;
        if (node < NN) nodes_out[node] = spart + g_cd[0];
    }
}

// ---------------------------------------------------------------------------
extern "C" void kernel_launch(void* const* d_in, const int* in_sizes, int n_in,
                              void* d_out, int out_size) {
    const float* nodes     = (const float*)d_in[0];
    const float* edges     = (const float*)d_in[1];
    const float* globals_  = (const float*)d_in[2];
    const int*   senders   = (const int*)d_in[3];
    const int*   receivers = (const int*)d_in[4];
    const float* W_en = (const float*)d_in[5];
    const float* b_en = (const float*)d_in[6];
    const float* W_ee = (const float*)d_in[7];
    const float* b_ee = (const float*)d_in[8];
    const float* W1   = (const float*)d_in[9];
    const float* b1   = (const float*)d_in[10];
    const float* W2   = (const float*)d_in[11];
    const float* b2   = (const float*)d_in[12];
    const float* W_dn = (const float*)d_in[13];
    const float* b_dn = (const float*)d_in[14];
    const float* W_de = (const float*)d_in[15];
    const float* b_de = (const float*)d_in[16];

    float* out = (float*)d_out;
    float* nodes_out = out;          // [50000]
    float* edges_out = out + NN;     // [800000]

    void* p = nullptr;
    cudaGetSymbolAddress(&p, g_agg);
    cudaMemsetAsync(p, 0, (size_t)NN * 8 * sizeof(float), 0);
    cudaGetSymbolAddress(&p, g_W1b);
    cudaMemsetAsync(p, 0, L * 64 * sizeof(__nv_bfloat16), 0);

    edge_kernel<<<(NE + 255) / 256, 256>>>(
        edges, senders, receivers, edges_out, globals_, W_en, b_en, W_ee, b_ee,
        W1, b1, W2, b2, W_dn, b_dn, W_de, b_de);
    node_tc_kernel<<<NB, 128>>>(nodes, nodes_out);
}

// round 14
// speedup vs baseline: 1.0933x; 1.0609x over previous
#include <cuda_runtime.h>
#include <cstdint>

#define NN 50000
#define NE 800000
#define L 128
#define KEFF 24     // 16 node feats + 3 agg_s + 1 cnt_s + 3 agg_r + 1 cnt_r
#define JP (L / 2)  // 64 packed hidden-unit pairs
#define GRID 888    // 148 SMs x 6 resident CTAs (guaranteed by launch_bounds)
#define BLK 128
#define NTHREADS (GRID * BLK)

// Scratch (__device__ globals; no allocation allowed; zero-initialized)
__device__ float g_agg[NN * 8];       // per node: {s0,s1,s2,cnt_s, r0,r1,r2,cnt_r}
__device__ float g_W1eff[L * KEFF];   // [j*24+k] folded layer-1 weight
__device__ float g_b1eff[L];          // folded layer-1 bias
__device__ float g_w2d[L];            // W2 @ W_dn
__device__ float g_cd[1];             // b2.W_dn + b_dn
__device__ unsigned g_bar_count;
__device__ volatile unsigned g_bar_gen;

// f32x2 packed helpers ------------------------------------------------------
__device__ __forceinline__ unsigned long long pk2(float lo, float hi) {
    unsigned long long r;
    asm("mov.b64 %0, {%1, %2};" : "=l"(r) : "f"(lo), "f"(hi));
    return r;
}
__device__ __forceinline__ void upk2(unsigned long long v, float& lo, float& hi) {
    asm("mov.b64 {%0, %1}, %2;" : "=f"(lo), "=f"(hi) : "l"(v));
}
#define FMA2(d, a, b, c) \
    asm("fma.rn.f32x2 %0, %1, %2, %3;" : "=l"(d) : "l"(a), "l"(b), "l"(c))
#define ADD2(d, a, b) \
    asm("add.rn.f32x2 %0, %1, %2;" : "=l"(d) : "l"(a), "l"(b))

__device__ __forceinline__ float warp_sum(float v) {
#pragma unroll
    for (int o = 16; o; o >>= 1) v += __shfl_xor_sync(0xffffffffu, v, o);
    return v;
}

// Device-wide barrier: sense-reversal on a monotonically increasing gen.
// Safe across graph replays (gen never resets; count resets each use).
__device__ __forceinline__ void grid_barrier() {
    __threadfence();
    __syncthreads();
    if (threadIdx.x == 0) {
        unsigned gen = g_bar_gen;  // read BEFORE arriving
        unsigned arrived = atomicAdd(&g_bar_count, 1u) + 1u;
        if (arrived == GRID) {
            g_bar_count = 0;
            __threadfence();
            g_bar_gen = gen + 1;
        } else {
            while (g_bar_gen == gen) {
            }
        }
    }
    __syncthreads();
    __threadfence();
}

// ---------------------------------------------------------------------------
// Fused persistent kernel: phase0 zero+folds -> bar -> phase1 edges -> bar ->
// phase2 nodes (R6 scalar f32x2 math, CTAs 0..390, 1 node/thread).
__global__ __launch_bounds__(BLK, 6) void fused_kernel(
    const float* __restrict__ nodes, const float* __restrict__ edges,
    const float* __restrict__ g, const int* __restrict__ senders,
    const int* __restrict__ receivers, const float* __restrict__ W_en,
    const float* __restrict__ b_en, const float* __restrict__ W_ee,
    const float* __restrict__ b_ee, const float* __restrict__ W1,
    const float* __restrict__ b1, const float* __restrict__ W2,
    const float* __restrict__ b2, const float* __restrict__ W_dn,
    const float* __restrict__ b_dn, const float* __restrict__ W_de,
    const float* __restrict__ b_de, float* __restrict__ nodes_out,
    float* __restrict__ edges_out) {
    __shared__ float s_edec[4];
    __shared__ unsigned long long sWp[JP * KEFF];  // {w[2j][k], w[2j+1][k]}, 12 KB
    __shared__ unsigned long long sBp[JP];
    __shared__ unsigned long long sDp[JP];

    int tid = threadIdx.x;
    int lane = tid & 31;
    int warp = tid >> 5;
    int gtid = blockIdx.x * BLK + tid;

    // ---------------- phase 0: per-CTA edec + distributed folds + zero agg --
    {
        // per-CTA edge-decoder fold (4 warps)
        float acc = 0.f;
        const float* A = (warp < 3) ? (W_ee + warp * L) : b_ee;
#pragma unroll
        for (int q = 0; q < 4; q++) {
            int m = lane + 32 * q;
            acc += A[m] * W_de[m];
        }
        acc = warp_sum(acc);
        if (lane == 0) s_edec[warp] = (warp == 3) ? acc + b_de[0] : acc;
    }

    int gw = blockIdx.x * 4 + warp;  // 3552 warp-jobs available, 3329 needed
    if (gw < L * KEFF) {             // W1eff[j][k]
        int k = gw >> 7;
        int j = gw & (L - 1);
        const float* A;
        int base;
        if (k < 16)      { A = W_en + k * L;        base = 0; }
        else if (k < 19) { A = W_ee + (k - 16) * L; base = L; }
        else if (k == 19){ A = b_ee;                base = L; }
        else if (k < 23) { A = W_ee + (k - 20) * L; base = 2 * L; }
        else             { A = b_ee;                base = 2 * L; }
        float acc = 0.f;
#pragma unroll
        for (int q = 0; q < 4; q++) {
            int m = lane + 32 * q;
            acc += A[m] * W1[(size_t)(base + m) * L + j];
        }
        acc = warp_sum(acc);
        if (lane == 0) g_W1eff[j * KEFF + k] = acc;
    } else if (gw < L * KEFF + L) {  // b1eff[j]
        int j = gw - L * KEFF;
        float acc = 0.f;
#pragma unroll
        for (int q = 0; q < 4; q++) {
            int m = lane + 32 * q;
            acc += b_en[m] * W1[(size_t)m * L + j];
        }
        if (lane < 8) acc += g[lane] * W1[(size_t)(3 * L + lane) * L + j];
        acc = warp_sum(acc);
        if (lane == 0) g_b1eff[j] = acc + b1[j];
    } else if (gw < L * KEFF + 2 * L) {  // w2d[k]
        int k = gw - L * KEFF - L;
        float acc = 0.f;
#pragma unroll
        for (int q = 0; q < 4; q++) {
            int j = lane + 32 * q;
            acc += W2[(size_t)k * L + j] * W_dn[j];
        }
        acc = warp_sum(acc);
        if (lane == 0) g_w2d[k] = acc;
    } else if (gw == L * KEFF + 2 * L) {  // cd
        float acc = 0.f;
#pragma unroll
        for (int q = 0; q < 4; q++) {
            int j = lane + 32 * q;
            acc += b2[j] * W_dn[j];
        }
        acc = warp_sum(acc);
        if (lane == 0) g_cd[0] = acc + b_dn[0];
    }

    // zero agg buffers (grid-stride float4)
    {
        float4 z = make_float4(0.f, 0.f, 0.f, 0.f);
        float4* a4 = reinterpret_cast<float4*>(g_agg);
        for (int i = gtid; i < NN * 2; i += NTHREADS) a4[i] = z;
    }

    grid_barrier();

    // ---------------- phase 1: edges ---------------------------------------
    {
        float w0 = s_edec[0], w1 = s_edec[1], w2 = s_edec[2], c = s_edec[3];
        for (int e = gtid; e < NE; e += NTHREADS) {
            float x0 = __ldg(edges + 3 * e + 0);
            float x1 = __ldg(edges + 3 * e + 1);
            float x2 = __ldg(edges + 3 * e + 2);
            int s = senders[e];
            int r = receivers[e];

            float* ps = g_agg + (size_t)8 * s;
            float* pr = g_agg + (size_t)8 * r + 4;
            asm volatile("red.global.add.v4.f32 [%0], {%1, %2, %3, %4};" ::"l"(
                             ps),
                         "f"(x0), "f"(x1), "f"(x2), "f"(1.0f)
                         : "memory");
            asm volatile("red.global.add.v4.f32 [%0], {%1, %2, %3, %4};" ::"l"(
                             pr),
                         "f"(x0), "f"(x1), "f"(x2), "f"(1.0f)
                         : "memory");

            edges_out[e] = fmaf(x0, w0, fmaf(x1, w1, fmaf(x2, w2, c)));
        }
    }

    grid_barrier();

    // ---------------- phase 2: nodes (R6 scalar f32x2, CTAs 0..390) --------
    if (blockIdx.x * BLK >= NN + BLK - 1 && blockIdx.x * BLK >= NN) return;
    if (blockIdx.x >= (NN + BLK - 1) / BLK) return;

    for (int i = tid; i < JP * KEFF; i += BLK) {
        int jp = i / KEFF;
        int k = i - jp * KEFF;
        sWp[i] = pk2(g_W1eff[(2 * jp) * KEFF + k],
                     g_W1eff[(2 * jp + 1) * KEFF + k]);
    }
    if (tid < JP) {
        sBp[tid] = pk2(g_b1eff[2 * tid], g_b1eff[2 * tid + 1]);
        sDp[tid] = pk2(g_w2d[2 * tid], g_w2d[2 * tid + 1]);
    }
    __syncthreads();

    int n = blockIdx.x * BLK + tid;
    if (n >= NN) return;

    // 24 inputs, each packed {x,x}
    unsigned long long in2[KEFF];
    {
        const float4* np = reinterpret_cast<const float4*>(nodes + (size_t)n * 16);
#pragma unroll
        for (int q = 0; q < 4; q++) {
            float4 v = __ldg(np + q);
            in2[4 * q + 0] = pk2(v.x, v.x);
            in2[4 * q + 1] = pk2(v.y, v.y);
            in2[4 * q + 2] = pk2(v.z, v.z);
            in2[4 * q + 3] = pk2(v.w, v.w);
        }
        const float4* pa = reinterpret_cast<const float4*>(g_agg + (size_t)8 * n);
        float4 a0 = pa[0], a1 = pa[1];
        in2[16] = pk2(a0.x, a0.x); in2[17] = pk2(a0.y, a0.y);
        in2[18] = pk2(a0.z, a0.z); in2[19] = pk2(a0.w, a0.w);
        in2[20] = pk2(a1.x, a1.x); in2[21] = pk2(a1.y, a1.y);
        in2[22] = pk2(a1.z, a1.z); in2[23] = pk2(a1.w, a1.w);
    }

    unsigned long long out2 = 0;

#pragma unroll 4
    for (int jp = 0; jp < JP; jp++) {
        unsigned long long acca = sBp[jp];
        unsigned long long accb = 0;
        const ulonglong2* wr = reinterpret_cast<const ulonglong2*>(sWp + jp * KEFF);
#pragma unroll
        for (int q = 0; q < 6; q++) {
            ulonglong2 w = wr[2 * q];
            ulonglong2 w2v = wr[2 * q + 1];
            FMA2(acca, in2[4 * q + 0], w.x, acca);
            FMA2(accb, in2[4 * q + 1], w.y, accb);
            FMA2(acca, in2[4 * q + 2], w2v.x, acca);
            FMA2(accb, in2[4 * q + 3], w2v.y, accb);
        }
        unsigned long long acc;
        ADD2(acc, acca, accb);
        float lo, hi;
        upk2(acc, lo, hi);
        unsigned long long r2 = pk2(fmaxf(lo, 0.f), fmaxf(hi, 0.f));
        FMA2(out2, r2, sDp[jp], out2);
    }

    float o0, o1;
    upk2(out2, o0, o1);
    nodes_out[n] = o0 + o1 + g_cd[0];
}

// ---------------------------------------------------------------------------
extern "C" void kernel_launch(void* const* d_in, const int* in_sizes, int n_in,
                              void* d_out, int out_size) {
    const float* nodes     = (const float*)d_in[0];
    const float* edges     = (const float*)d_in[1];
    const float* globals_  = (const float*)d_in[2];
    const int*   senders   = (const int*)d_in[3];
    const int*   receivers = (const int*)d_in[4];
    const float* W_en = (const float*)d_in[5];
    const float* b_en = (const float*)d_in[6];
    const float* W_ee = (const float*)d_in[7];
    const float* b_ee = (const float*)d_in[8];
    const float* W1   = (const float*)d_in[9];
    const float* b1   = (const float*)d_in[10];
    const float* W2   = (const float*)d_in[11];
    const float* b2   = (const float*)d_in[12];
    const float* W_dn = (const float*)d_in[13];
    const float* b_dn = (const float*)d_in[14];
    const float* W_de = (const float*)d_in[15];
    const float* b_de = (const float*)d_in[16];

    float* out = (float*)d_out;
    float* nodes_out = out;          // [50000]
    float* edges_out = out + NN;     // [800000]

    fused_kernel<<<GRID, BLK>>>(nodes, edges, globals_, senders, receivers,
                                W_en, b_en, W_ee, b_ee, W1, b1, W2, b2, W_dn,
                                b_dn, W_de, b_de, nodes_out, edges_out);
}

// round 15
// speedup vs baseline: 1.4017x; 1.2820x over previous
#include <cuda_runtime.h>

#define NN 50000
#define NE 800000
#define L 128
#define KEFF 24     // 16 node feats + 3 agg_s + 1 cnt_s + 3 agg_r + 1 cnt_r
#define JP (L / 2)  // 64 packed hidden-unit pairs

// Scratch (__device__ globals; zero-initialized at module load).
// INVARIANT: g_agg is all-zero at entry of every kernel_launch execution —
// node_kernel re-zeroes each slot after consuming it.
__device__ float g_agg[NN * 8];       // per node: {s0,s1,s2,cnt_s, r0,r1,r2,cnt_r}
__device__ float g_W1eff[L * KEFF];   // [j*24+k] folded layer-1 weight
__device__ float g_b1eff[L];          // folded layer-1 bias
__device__ float g_w2d[L];            // W2 @ W_dn
__device__ float g_cd[1];             // b2.W_dn + b_dn

// f32x2 packed helpers ------------------------------------------------------
__device__ __forceinline__ unsigned long long pk2(float lo, float hi) {
    unsigned long long r;
    asm("mov.b64 %0, {%1, %2};" : "=l"(r) : "f"(lo), "f"(hi));
    return r;
}
__device__ __forceinline__ void upk2(unsigned long long v, float& lo, float& hi) {
    asm("mov.b64 {%0, %1}, %2;" : "=f"(lo), "=f"(hi) : "l"(v));
}
#define FMA2(d, a, b, c) \
    asm("fma.rn.f32x2 %0, %1, %2, %3;" : "=l"(d) : "l"(a), "l"(b), "l"(c))
#define ADD2(d, a, b) \
    asm("add.rn.f32x2 %0, %1, %2;" : "=l"(d) : "l"(a), "l"(b))

__device__ __forceinline__ float warp_sum(float v) {
#pragma unroll
    for (int o = 16; o; o >>= 1) v += __shfl_xor_sync(0xffffffffu, v, o);
    return v;
}

// ---------------------------------------------------------------------------
// Edge pass + embedded prep folds (R6, unchanged).
__global__ __launch_bounds__(256) void edge_kernel(
    const float* __restrict__ edges, const int* __restrict__ senders,
    const int* __restrict__ receivers, float* __restrict__ edges_out,
    const float* __restrict__ g, const float* __restrict__ W_en,
    const float* __restrict__ b_en, const float* __restrict__ W_ee,
    const float* __restrict__ b_ee, const float* __restrict__ W1,
    const float* __restrict__ b1, const float* __restrict__ W2,
    const float* __restrict__ b2, const float* __restrict__ W_dn,
    const float* __restrict__ b_dn, const float* __restrict__ W_de,
    const float* __restrict__ b_de) {
    __shared__ float s_edec[4];
    int tid = threadIdx.x;
    int lane = tid & 31;
    int warp = tid >> 5;

    if (warp < 4) {
        float acc = 0.f;
        const float* A = (warp < 3) ? (W_ee + warp * L) : b_ee;
#pragma unroll
        for (int q = 0; q < 4; q++) {
            int m = lane + 32 * q;
            acc += A[m] * W_de[m];
        }
        acc = warp_sum(acc);
        if (lane == 0) s_edec[warp] = (warp == 3) ? acc + b_de[0] : acc;
    }

    int gw = blockIdx.x * 8 + warp;
    if (gw < L * KEFF) {
        int k = gw >> 7;
        int j = gw & (L - 1);
        const float* A;
        int base;
        if (k < 16)      { A = W_en + k * L;        base = 0; }
        else if (k < 19) { A = W_ee + (k - 16) * L; base = L; }
        else if (k == 19){ A = b_ee;                base = L; }
        else if (k < 23) { A = W_ee + (k - 20) * L; base = 2 * L; }
        else             { A = b_ee;                base = 2 * L; }
        float acc = 0.f;
#pragma unroll
        for (int q = 0; q < 4; q++) {
            int m = lane + 32 * q;
            acc += A[m] * W1[(size_t)(base + m) * L + j];
        }
        acc = warp_sum(acc);
        if (lane == 0) g_W1eff[j * KEFF + k] = acc;
    } else if (gw < L * KEFF + L) {
        int j = gw - L * KEFF;
        float acc = 0.f;
#pragma unroll
        for (int q = 0; q < 4; q++) {
            int m = lane + 32 * q;
            acc += b_en[m] * W1[(size_t)m * L + j];
        }
        if (lane < 8) acc += g[lane] * W1[(size_t)(3 * L + lane) * L + j];
        acc = warp_sum(acc);
        if (lane == 0) g_b1eff[j] = acc + b1[j];
    } else if (gw < L * KEFF + 2 * L) {
        int k = gw - L * KEFF - L;
        float acc = 0.f;
#pragma unroll
        for (int q = 0; q < 4; q++) {
            int j = lane + 32 * q;
            acc += W2[(size_t)k * L + j] * W_dn[j];
        }
        acc = warp_sum(acc);
        if (lane == 0) g_w2d[k] = acc;
    } else if (gw == L * KEFF + 2 * L) {
        float acc = 0.f;
#pragma unroll
        for (int q = 0; q < 4; q++) {
            int j = lane + 32 * q;
            acc += b2[j] * W_dn[j];
        }
        acc = warp_sum(acc);
        if (lane == 0) g_cd[0] = acc + b_dn[0];
    }
    __syncthreads();

    int e = blockIdx.x * blockDim.x + tid;
    if (e >= NE) return;

    float w0 = s_edec[0], w1 = s_edec[1], w2 = s_edec[2], c = s_edec[3];

    float x0 = __ldg(edges + 3 * e + 0);
    float x1 = __ldg(edges + 3 * e + 1);
    float x2 = __ldg(edges + 3 * e + 2);
    int s = senders[e];
    int r = receivers[e];

    float* ps = g_agg + (size_t)8 * s;
    float* pr = g_agg + (size_t)8 * r + 4;
    asm volatile("red.global.add.v4.f32 [%0], {%1, %2, %3, %4};" ::"l"(ps),
                 "f"(x0), "f"(x1), "f"(x2), "f"(1.0f)
                 : "memory");
    asm volatile("red.global.add.v4.f32 [%0], {%1, %2, %3, %4};" ::"l"(pr),
                 "f"(x0), "f"(x1), "f"(x2), "f"(1.0f)
                 : "memory");

    edges_out[e] = fmaf(x0, w0, fmaf(x1, w1, fmaf(x2, w2, c)));
}

// ---------------------------------------------------------------------------
// Node pass: R6 math, but per-jp weight loads are BATCHED into registers
// (w[12] = 48 regs) before the FMA2 block, and the output accumulator is
// split even/odd. No launch_bounds reg clamp — grid is CTA-bound anyway.
// Also re-zeroes each thread's g_agg slot (replay invariant; replaces memset).
__global__ void node_kernel(const float* __restrict__ nodes,
                            float* __restrict__ nodes_out) {
    __shared__ unsigned long long sWp[JP * KEFF];  // {w[2j][k], w[2j+1][k]}, 12 KB
    __shared__ unsigned long long sBp[JP];
    __shared__ unsigned long long sDp[JP];

    int tid = threadIdx.x;
    for (int i = tid; i < JP * KEFF; i += blockDim.x) {
        int jp = i / KEFF;
        int k = i - jp * KEFF;
        sWp[i] = pk2(g_W1eff[(2 * jp) * KEFF + k], g_W1eff[(2 * jp + 1) * KEFF + k]);
    }
    if (tid < JP) {
        sBp[tid] = pk2(g_b1eff[2 * tid], g_b1eff[2 * tid + 1]);
        sDp[tid] = pk2(g_w2d[2 * tid], g_w2d[2 * tid + 1]);
    }
    __syncthreads();

    int n = blockIdx.x * blockDim.x + tid;
    if (n >= NN) return;

    // 24 inputs, each packed {x,x}; re-zero agg slot after reading.
    unsigned long long in2[KEFF];
    {
        const float4* np = reinterpret_cast<const float4*>(nodes + (size_t)n * 16);
#pragma unroll
        for (int q = 0; q < 4; q++) {
            float4 v = __ldg(np + q);
            in2[4 * q + 0] = pk2(v.x, v.x);
            in2[4 * q + 1] = pk2(v.y, v.y);
            in2[4 * q + 2] = pk2(v.z, v.z);
            in2[4 * q + 3] = pk2(v.w, v.w);
        }
        float4* pa = reinterpret_cast<float4*>(g_agg + (size_t)8 * n);
        float4 a0 = pa[0], a1 = pa[1];
        float4 z = make_float4(0.f, 0.f, 0.f, 0.f);
        pa[0] = z;
        pa[1] = z;
        in2[16] = pk2(a0.x, a0.x); in2[17] = pk2(a0.y, a0.y);
        in2[18] = pk2(a0.z, a0.z); in2[19] = pk2(a0.w, a0.w);
        in2[20] = pk2(a1.x, a1.x); in2[21] = pk2(a1.y, a1.y);
        in2[22] = pk2(a1.z, a1.z); in2[23] = pk2(a1.w, a1.w);
    }

    unsigned long long outE = 0, outO = 0;

#pragma unroll 2
    for (int jp = 0; jp < JP; jp += 2) {
#pragma unroll
        for (int sub = 0; sub < 2; sub++) {
            int j = jp + sub;
            // batch ALL 12 weight vectors for this j into registers first
            ulonglong2 w[12];
            const ulonglong2* wr =
                reinterpret_cast<const ulonglong2*>(sWp + j * KEFF);
#pragma unroll
            for (int q = 0; q < 12; q++) w[q] = wr[q];

            unsigned long long acca = sBp[j];
            unsigned long long accb = 0;
#pragma unroll
            for (int q = 0; q < 6; q++) {
                FMA2(acca, in2[4 * q + 0], w[2 * q].x, acca);
                FMA2(accb, in2[4 * q + 1], w[2 * q].y, accb);
                FMA2(acca, in2[4 * q + 2], w[2 * q + 1].x, acca);
                FMA2(accb, in2[4 * q + 3], w[2 * q + 1].y, accb);
            }
            unsigned long long acc;
            ADD2(acc, acca, accb);
            float lo, hi;
            upk2(acc, lo, hi);
            unsigned long long r2 = pk2(fmaxf(lo, 0.f), fmaxf(hi, 0.f));
            if (sub == 0) {
                FMA2(outE, r2, sDp[j], outE);
            } else {
                FMA2(outO, r2, sDp[j], outO);
            }
        }
    }

    unsigned long long out2;
    ADD2(out2, outE, outO);
    float o0, o1;
    upk2(out2, o0, o1);
    nodes_out[n] = o0 + o1 + g_cd[0];
}

// ---------------------------------------------------------------------------
extern "C" void kernel_launch(void* const* d_in, const int* in_sizes, int n_in,
                              void* d_out, int out_size) {
    const float* nodes     = (const float*)d_in[0];
    const float* edges     = (const float*)d_in[1];
    const float* globals_  = (const float*)d_in[2];
    const int*   senders   = (const int*)d_in[3];
    const int*   receivers = (const int*)d_in[4];
    const float* W_en = (const float*)d_in[5];
    const float* b_en = (const float*)d_in[6];
    const float* W_ee = (const float*)d_in[7];
    const float* b_ee = (const float*)d_in[8];
    const float* W1   = (const float*)d_in[9];
    const float* b1   = (const float*)d_in[10];
    const float* W2   = (const float*)d_in[11];
    const float* b2   = (const float*)d_in[12];
    const float* W_dn = (const float*)d_in[13];
    const float* b_dn = (const float*)d_in[14];
    const float* W_de = (const float*)d_in[15];
    const float* b_de = (const float*)d_in[16];

    float* out = (float*)d_out;
    float* nodes_out = out;          // [50000]
    float* edges_out = out + NN;     // [800000]

    // NOTE: no memset — g_agg starts zeroed (module load) and node_kernel
    // re-zeroes each slot after consuming it, so every execution (first run,
    // capture, and all graph replays) sees a zeroed buffer.
    edge_kernel<<<(NE + 255) / 256, 256>>>(
        edges, senders, receivers, edges_out, globals_, W_en, b_en, W_ee, b_ee,
        W1, b1, W2, b2, W_dn, b_dn, W_de, b_de);
    node_kernel<<<(NN + 127) / 128, 128>>>(nodes, nodes_out);
}

// round 16
// speedup vs baseline: 1.4786x; 1.0549x over previous
#include <cuda_runtime.h>

#define NN 50000
#define NE 800000
#define L 128
#define KEFF 24     // 16 node feats + 3 agg_s + 1 cnt_s + 3 agg_r + 1 cnt_r
#define JP (L / 2)  // 64 packed hidden-unit pairs

// Scratch (__device__ globals; zero-initialized at module load).
// INVARIANT: g_agg is all-zero at entry of every kernel_launch execution —
// node_kernel re-zeroes each slot after consuming it.
__device__ float g_agg[NN * 8];       // per node: {s0,s1,s2,cnt_s, r0,r1,r2,cnt_r}
__device__ float g_W1eff[L * KEFF];   // [j*24+k] folded layer-1 weight
__device__ float g_b1eff[L];          // folded layer-1 bias
__device__ float g_w2d[L];            // W2 @ W_dn
__device__ float g_cd[1];             // b2.W_dn + b_dn

// f32x2 packed helpers ------------------------------------------------------
__device__ __forceinline__ unsigned long long pk2(float lo, float hi) {
    unsigned long long r;
    asm("mov.b64 %0, {%1, %2};" : "=l"(r) : "f"(lo), "f"(hi));
    return r;
}
__device__ __forceinline__ void upk2(unsigned long long v, float& lo, float& hi) {
    asm("mov.b64 {%0, %1}, %2;" : "=f"(lo), "=f"(hi) : "l"(v));
}
#define FMA2(d, a, b, c) \
    asm("fma.rn.f32x2 %0, %1, %2, %3;" : "=l"(d) : "l"(a), "l"(b), "l"(c))
#define ADD2(d, a, b) \
    asm("add.rn.f32x2 %0, %1, %2;" : "=l"(d) : "l"(a), "l"(b))

__device__ __forceinline__ float warp_sum(float v) {
#pragma unroll
    for (int o = 16; o; o >>= 1) v += __shfl_xor_sync(0xffffffffu, v, o);
    return v;
}

// ---------------------------------------------------------------------------
// Edge pass + embedded prep folds.
// Folds are transposed for coalescing: warp = (k, j-group), lane-parallel
// over j -> every W1 read is one coalesced 128B line. 229 fold warps total.
__global__ __launch_bounds__(256) void edge_kernel(
    const float* __restrict__ edges, const int* __restrict__ senders,
    const int* __restrict__ receivers, float* __restrict__ edges_out,
    const float* __restrict__ g, const float* __restrict__ W_en,
    const float* __restrict__ b_en, const float* __restrict__ W_ee,
    const float* __restrict__ b_ee, const float* __restrict__ W1,
    const float* __restrict__ b1, const float* __restrict__ W2,
    const float* __restrict__ b2, const float* __restrict__ W_dn,
    const float* __restrict__ b_dn, const float* __restrict__ W_de,
    const float* __restrict__ b_de) {
    __shared__ float s_edec[4];
    int tid = threadIdx.x;
    int lane = tid & 31;
    int warp = tid >> 5;

    // per-block edge-decoder fold
    if (warp < 4) {
        float acc = 0.f;
        const float* A = (warp < 3) ? (W_ee + warp * L) : b_ee;
#pragma unroll
        for (int q = 0; q < 4; q++) {
            int m = lane + 32 * q;
            acc += A[m] * W_de[m];
        }
        acc = warp_sum(acc);
        if (lane == 0) s_edec[warp] = (warp == 3) ? acc + b_de[0] : acc;
    }

    // distributed folds (coalesced): gw 0..95 W1eff, 96..99 b1eff,
    // 100..227 w2d, 228 cd.
    int gw = blockIdx.x * 8 + warp;
    if (gw < 96) {  // W1eff[j][k], warp = (k, jg), lane = j within group
        int k = gw >> 2;     // 0..23
        int jg = gw & 3;
        int j = jg * 32 + lane;
        const float* A;
        int base;
        if (k < 16)      { A = W_en + k * L;        base = 0; }
        else if (k < 19) { A = W_ee + (k - 16) * L; base = L; }
        else if (k == 19){ A = b_ee;                base = L; }
        else if (k < 23) { A = W_ee + (k - 20) * L; base = 2 * L; }
        else             { A = b_ee;                base = 2 * L; }
        float acc = 0.f;
#pragma unroll 8
        for (int m = 0; m < L; m++)
            acc += A[m] * W1[(size_t)(base + m) * L + j];
        g_W1eff[j * KEFF + k] = acc;
    } else if (gw < 100) {  // b1eff[j]
        int j = (gw - 96) * 32 + lane;
        float acc = b1[j];
#pragma unroll 8
        for (int m = 0; m < L; m++) acc += b_en[m] * W1[(size_t)m * L + j];
#pragma unroll
        for (int m = 0; m < 8; m++)
            acc += g[m] * W1[(size_t)(3 * L + m) * L + j];
        g_b1eff[j] = acc;
    } else if (gw < 228) {  // w2d[k], lane-parallel over j (coalesced)
        int k = gw - 100;
        float acc = 0.f;
#pragma unroll
        for (int q = 0; q < 4; q++) {
            int j = lane + 32 * q;
            acc += W2[(size_t)k * L + j] * W_dn[j];
        }
        acc = warp_sum(acc);
        if (lane == 0) g_w2d[k] = acc;
    } else if (gw == 228) {  // cd
        float acc = 0.f;
#pragma unroll
        for (int q = 0; q < 4; q++) {
            int j = lane + 32 * q;
            acc += b2[j] * W_dn[j];
        }
        acc = warp_sum(acc);
        if (lane == 0) g_cd[0] = acc + b_dn[0];
    }
    __syncthreads();

    int e = blockIdx.x * blockDim.x + tid;
    if (e >= NE) return;

    float w0 = s_edec[0], w1 = s_edec[1], w2 = s_edec[2], c = s_edec[3];

    float x0 = __ldg(edges + 3 * e + 0);
    float x1 = __ldg(edges + 3 * e + 1);
    float x2 = __ldg(edges + 3 * e + 2);
    int s = senders[e];
    int r = receivers[e];

    float* ps = g_agg + (size_t)8 * s;
    float* pr = g_agg + (size_t)8 * r + 4;
    asm volatile("red.global.add.v4.f32 [%0], {%1, %2, %3, %4};" ::"l"(ps),
                 "f"(x0), "f"(x1), "f"(x2), "f"(1.0f)
                 : "memory");
    asm volatile("red.global.add.v4.f32 [%0], {%1, %2, %3, %4};" ::"l"(pr),
                 "f"(x0), "f"(x1), "f"(x2), "f"(1.0f)
                 : "memory");

    edges_out[e] = fmaf(x0, w0, fmaf(x1, w1, fmaf(x2, w2, c)));
}

// ---------------------------------------------------------------------------
// Node pass: R6/R15 math with a TRUE software-pipelined weight double-buffer.
// Body: prefetch wB(jp+1) -> FMA(wA,jp) -> prefetch wA(jp+2) -> FMA(wB,jp+1).
// Loads of one buffer are independent of the other's FMAs, so ptxas cannot
// re-serialize into load-use chains. launch_bounds(128,3) caps regs at 170
// (3 CTAs/SM guaranteed; grid 391 needs only 2.64/SM -> one wave).
__global__ __launch_bounds__(128, 3) void node_kernel(
    const float* __restrict__ nodes, float* __restrict__ nodes_out) {
    __shared__ unsigned long long sWp[JP * KEFF];  // {w[2j][k], w[2j+1][k]}, 12 KB
    __shared__ unsigned long long sBp[JP];
    __shared__ unsigned long long sDp[JP];

    int tid = threadIdx.x;
    for (int i = tid; i < JP * KEFF; i += blockDim.x) {
        int jp = i / KEFF;
        int k = i - jp * KEFF;
        sWp[i] = pk2(g_W1eff[(2 * jp) * KEFF + k], g_W1eff[(2 * jp + 1) * KEFF + k]);
    }
    if (tid < JP) {
        sBp[tid] = pk2(g_b1eff[2 * tid], g_b1eff[2 * tid + 1]);
        sDp[tid] = pk2(g_w2d[2 * tid], g_w2d[2 * tid + 1]);
    }
    __syncthreads();

    int n = blockIdx.x * blockDim.x + tid;
    if (n >= NN) return;

    // 24 inputs, each packed {x,x}; re-zero agg slot after reading.
    unsigned long long in2[KEFF];
    {
        const float4* np = reinterpret_cast<const float4*>(nodes + (size_t)n * 16);
#pragma unroll
        for (int q = 0; q < 4; q++) {
            float4 v = __ldg(np + q);
            in2[4 * q + 0] = pk2(v.x, v.x);
            in2[4 * q + 1] = pk2(v.y, v.y);
            in2[4 * q + 2] = pk2(v.z, v.z);
            in2[4 * q + 3] = pk2(v.w, v.w);
        }
        float4* pa = reinterpret_cast<float4*>(g_agg + (size_t)8 * n);
        float4 a0 = pa[0], a1 = pa[1];
        float4 z = make_float4(0.f, 0.f, 0.f, 0.f);
        pa[0] = z;
        pa[1] = z;
        in2[16] = pk2(a0.x, a0.x); in2[17] = pk2(a0.y, a0.y);
        in2[18] = pk2(a0.z, a0.z); in2[19] = pk2(a0.w, a0.w);
        in2[20] = pk2(a1.x, a1.x); in2[21] = pk2(a1.y, a1.y);
        in2[22] = pk2(a1.z, a1.z); in2[23] = pk2(a1.w, a1.w);
    }

    const ulonglong2* wr = reinterpret_cast<const ulonglong2*>(sWp);
    ulonglong2 wA[12], wB[12];
#pragma unroll
    for (int q = 0; q < 12; q++) wA[q] = wr[q];  // jp 0

    unsigned long long outE = 0, outO = 0;

    for (int jp = 0; jp < JP; jp += 2) {
        // prefetch jp+1 into wB
#pragma unroll
        for (int q = 0; q < 12; q++) wB[q] = wr[(jp + 1) * 12 + q];

        // compute jp with wA
        {
            unsigned long long acca = sBp[jp];
            unsigned long long accb = 0;
#pragma unroll
            for (int q = 0; q < 6; q++) {
                FMA2(acca, in2[4 * q + 0], wA[2 * q].x, acca);
                FMA2(accb, in2[4 * q + 1], wA[2 * q].y, accb);
                FMA2(acca, in2[4 * q + 2], wA[2 * q + 1].x, acca);
                FMA2(accb, in2[4 * q + 3], wA[2 * q + 1].y, accb);
            }
            unsigned long long acc;
            ADD2(acc, acca, accb);
            float lo, hi;
            upk2(acc, lo, hi);
            unsigned long long r2 = pk2(fmaxf(lo, 0.f), fmaxf(hi, 0.f));
            FMA2(outE, r2, sDp[jp], outE);
        }

        // prefetch jp+2 into wA (wrap on last iter; extra loads harmless)
#pragma unroll
        for (int q = 0; q < 12; q++) wA[q] = wr[((jp + 2) & (JP - 1)) * 12 + q];

        // compute jp+1 with wB
        {
            unsigned long long acca = sBp[jp + 1];
            unsigned long long accb = 0;
#pragma unroll
            for (int q = 0; q < 6; q++) {
                FMA2(acca, in2[4 * q + 0], wB[2 * q].x, acca);
                FMA2(accb, in2[4 * q + 1], wB[2 * q].y, accb);
                FMA2(acca, in2[4 * q + 2], wB[2 * q + 1].x, acca);
                FMA2(accb, in2[4 * q + 3], wB[2 * q + 1].y, accb);
            }
            unsigned long long acc;
            ADD2(acc, acca, accb);
            float lo, hi;
            upk2(acc, lo, hi);
            unsigned long long r2 = pk2(fmaxf(lo, 0.f), fmaxf(hi, 0.f));
            FMA2(outO, r2, sDp[jp + 1], outO);
        }
    }

    unsigned long long out2;
    ADD2(out2, outE, outO);
    float o0, o1;
    upk2(out2, o0, o1);
    nodes_out[n] = o0 + o1 + g_cd[0];
}

// ---------------------------------------------------------------------------
extern "C" void kernel_launch(void* const* d_in, const int* in_sizes, int n_in,
                              void* d_out, int out_size) {
    const float* nodes     = (const float*)d_in[0];
    const float* edges     = (const float*)d_in[1];
    const float* globals_  = (const float*)d_in[2];
    const int*   senders   = (const int*)d_in[3];
    const int*   receivers = (const int*)d_in[4];
    const float* W_en = (const float*)d_in[5];
    const float* b_en = (const float*)d_in[6];
    const float* W_ee = (const float*)d_in[7];
    const float* b_ee = (const float*)d_in[8];
    const float* W1   = (const float*)d_in[9];
    const float* b1   = (const float*)d_in[10];
    const float* W2   = (const float*)d_in[11];
    const float* b2   = (const float*)d_in[12];
    const float* W_dn = (const float*)d_in[13];
    const float* b_dn = (const float*)d_in[14];
    const float* W_de = (const float*)d_in[15];
    const float* b_de = (const float*)d_in[16];

    float* out = (float*)d_out;
    float* nodes_out = out;          // [50000]
    float* edges_out = out + NN;     // [800000]

    // NOTE: no memset — g_agg starts zeroed (module load) and node_kernel
    // re-zeroes each slot after consuming it, so every execution (first run,
    // capture, and all graph replays) sees a zeroed buffer.
    edge_kernel<<<(NE + 255) / 256, 256>>>(
        edges, senders, receivers, edges_out, globals_, W_en, b_en, W_ee, b_ee,
        W1, b1, W2, b2, W_dn, b_dn, W_de, b_de);
    node_kernel<<<(NN + 127) / 128, 128>>>(nodes, nodes_out);
}